// round 8
// baseline (speedup 1.0000x reference)
#include <cuda_runtime.h>
#include <cuda_bf16.h>
#include <math.h>
#include <stdint.h>

// ---------------- problem constants ----------------
#define NN      65536
#define CH      256      // IN_CH == GNN_DIM
#define GG      64
#define NPG     1024
#define KEIG    32
#define NB      64
#define BD      4
#define NBP     384
#define LAYERS  2

#define WTOT    491520
#define OFF_ENC   0
#define OFF_SELF0 65536
#define OFF_SELF1 131072
#define OFF_NB0   196608
#define OFF_NB1   262144
#define OFF_DEC   327680
#define OFF_LIN   425984

// ---------------- scratch (device globals; no mallocs allowed) -------------
__device__ float g_h  [NN * CH];
__device__ float g_tmp[NN * CH];
__device__ float g_agg[NN * CH];
__device__ float g_rep[NN * NBP];   // also used as agg scratch for layer 1
__device__ float g_hs [GG * KEIG * CH];
__device__ __nv_bfloat16 g_whi[WTOT];
__device__ __nv_bfloat16 g_wlo[WTOT];

__device__ __forceinline__ float gelu_exact(float x) {
    return 0.5f * x * (1.0f + erff(x * 0.7071067811865476f));
}
__device__ __forceinline__ uint32_t pack_bf2(float a, float b) {
    __nv_bfloat162 t = __floats2bfloat162_rn(a, b);
    return *(uint32_t*)&t;
}
__device__ __forceinline__ uint32_t smem_u32(const void* p) {
    uint32_t a;
    asm("{ .reg .u64 t; cvta.to.shared.u64 t, %1; cvt.u32.u64 %0, t; }" : "=r"(a) : "l"(p));
    return a;
}
__device__ __forceinline__ void ldsm_x4(uint32_t* r, uint32_t addr) {
    asm volatile("ldmatrix.sync.aligned.m8n8.x4.shared.b16 {%0,%1,%2,%3}, [%4];"
                 : "=r"(r[0]), "=r"(r[1]), "=r"(r[2]), "=r"(r[3]) : "r"(addr));
}
__device__ __forceinline__ void mma_bf16(float* c, const uint32_t* a, uint32_t b0, uint32_t b1) {
    asm volatile("mma.sync.aligned.m16n8k16.row.col.f32.bf16.bf16.f32 "
                 "{%0,%1,%2,%3}, {%4,%5,%6,%7}, {%8,%9}, {%0,%1,%2,%3};"
                 : "+f"(c[0]), "+f"(c[1]), "+f"(c[2]), "+f"(c[3])
                 : "r"(a[0]), "r"(a[1]), "r"(a[2]), "r"(a[3]), "r"(b0), "r"(b1));
}

// ---------------- fused weight convert+transpose (single launch) -----------
__global__ void convert_all(const float* __restrict__ enc, const float* __restrict__ selfw,
                            const float* __restrict__ nbw, const float* __restrict__ dec,
                            const float* __restrict__ lin,
                            __nv_bfloat16* __restrict__ dhi,
                            __nv_bfloat16* __restrict__ dlo) {
    int t = blockIdx.x * blockDim.x + threadIdx.x;
    if (t >= WTOT) return;
    const float* src;
    int local, Ncols, dstoff;
    if (t < OFF_SELF0)      { src = enc;            local = t;              Ncols = 256; dstoff = OFF_ENC; }
    else if (t < OFF_SELF1) { src = selfw;          local = t - OFF_SELF0;  Ncols = 256; dstoff = OFF_SELF0; }
    else if (t < OFF_NB0)   { src = selfw + 65536;  local = t - OFF_SELF1;  Ncols = 256; dstoff = OFF_SELF1; }
    else if (t < OFF_NB1)   { src = nbw;            local = t - OFF_NB0;    Ncols = 256; dstoff = OFF_NB0; }
    else if (t < OFF_DEC)   { src = nbw + 65536;    local = t - OFF_NB1;    Ncols = 256; dstoff = OFF_NB1; }
    else if (t < OFF_LIN)   { src = dec;            local = t - OFF_DEC;    Ncols = 384; dstoff = OFF_DEC; }
    else                    { src = lin;            local = t - OFF_LIN;    Ncols = 256; dstoff = OFF_LIN; }
    int k = local / Ncols, n = local % Ncols;
    float v = src[local];
    __nv_bfloat16 h = __float2bfloat16_rn(v);
    dhi[dstoff + (size_t)n * 256 + k] = h;
    dlo[dstoff + (size_t)n * 256 + k] = __float2bfloat16_rn(v - __bfloat162float(h));
}

// ---------------- edge scatter: agg[dst] += h[src] (vector red atomics) ----
__global__ void scatter_kernel(const float* __restrict__ h,
                               const int* __restrict__ ei,
                               float* __restrict__ agg, int E) {
    long t = (long)blockIdx.x * blockDim.x + threadIdx.x;
    if (t >= (long)E * 64) return;
    int e = (int)(t >> 6);
    int q = (int)(t & 63);
    int s = ei[e];
    int d = ei[E + e];
    float4 v = ((const float4*)(h + (size_t)s * CH))[q];
    float* dst = agg + (size_t)d * CH + q * 4;
    asm volatile("red.global.add.v4.f32 [%0], {%1, %2, %3, %4};"
                 :: "l"(dst), "f"(v.x), "f"(v.y), "f"(v.z), "f"(v.w)
                 : "memory");
}

// ---------------- HMMA GEMM (optionally dual-A fused layer) ----------------
// CTA tile 128x128, 8 warps as 2(M)x4(N), warp tile 64x32 (mi=4, nj=2).
// K chunks of 32. Split product: D = Ahi*Whi + Ahi*Wlo + Alo*Whi (fp32 accum).
// EPI 0: C = acc + bias1
// EPI 1: C = gelu(acc + bias1)
// EPI 2 (DUAL): C = gelu(acc + bias1 + bias2) + resid
#define PITCH 40   // bf16 per smem row (80 B) -> conflict-free ldmatrix

template <int EPI, int DUAL>
__global__ __launch_bounds__(256)
void tgemm(const float* __restrict__ A1, const float* __restrict__ A2,
           const __nv_bfloat16* __restrict__ W1hi, const __nv_bfloat16* __restrict__ W1lo,
           const __nv_bfloat16* __restrict__ W2hi, const __nv_bfloat16* __restrict__ W2lo,
           const float* __restrict__ bias1, const float* __restrict__ bias2,
           const float* __restrict__ resid,
           float* __restrict__ C, int Nn) {
    __shared__ __align__(16) __nv_bfloat16 sAhi[128 * PITCH];
    __shared__ __align__(16) __nv_bfloat16 sAlo[128 * PITCH];
    __shared__ __align__(16) __nv_bfloat16 sBhi[128 * PITCH];
    __shared__ __align__(16) __nv_bfloat16 sBlo[128 * PITCH];

    const int tid  = threadIdx.x;
    const int lane = tid & 31;
    const int wid  = tid >> 5;
    const int warpM = wid & 1;     // 2 warps over M (64 rows each)
    const int warpN = wid >> 1;    // 4 warps over N (32 cols each)
    const int rowBase = blockIdx.y * 128;
    const int colBase = blockIdx.x * 128;

    const float* Ab1 = A1 + (size_t)rowBase * 256;
    const float* Ab2 = DUAL ? A2 + (size_t)rowBase * 256 : nullptr;
    const __nv_bfloat16* Wh1 = W1hi + (size_t)colBase * 256;
    const __nv_bfloat16* Wl1 = W1lo + (size_t)colBase * 256;
    const __nv_bfloat16* Wh2 = DUAL ? W2hi + (size_t)colBase * 256 : nullptr;
    const __nv_bfloat16* Wl2 = DUAL ? W2lo + (size_t)colBase * 256 : nullptr;

    // hoisted ldmatrix base addresses (byte offsets within tiles)
    const uint32_t aFragOff = (uint32_t)(warpM * 64 + (lane & 15)) * (PITCH * 2)
                              + (lane >> 4) * 16;
    const int g = lane >> 3, lr = lane & 7;
    const uint32_t bFragOff = (uint32_t)(warpN * 32 + ((g >> 1) << 3) + lr) * (PITCH * 2)
                              + (g & 1) * 16;
    const uint32_t aHiB = smem_u32(sAhi) + aFragOff;
    const uint32_t aLoB = smem_u32(sAlo) + aFragOff;
    const uint32_t bHiB = smem_u32(sBhi) + bFragOff;
    const uint32_t bLoB = smem_u32(sBlo) + bFragOff;

    float c[4][4][4];
#pragma unroll
    for (int mi = 0; mi < 4; mi++)
#pragma unroll
        for (int ni = 0; ni < 4; ni++)
#pragma unroll
            for (int e = 0; e < 4; e++) c[mi][ni][e] = 0.f;

    // staging coords
    const int aR = tid >> 3;        // + i*32 (4 rows/thread)
    const int aKg = tid & 7;        // float4 group
    // B: idx = i*256+tid; row = idx>>2, grp = idx&3 (uint4 = 8 bf16)

    const int NCHUNK = DUAL ? 16 : 8;

    float4 pa[4];
    uint4  pbh[2], pbl[2];
#pragma unroll
    for (int i = 0; i < 4; i++)
        pa[i] = *(const float4*)&Ab1[(size_t)(aR + i * 32) * 256 + aKg * 4];
#pragma unroll
    for (int i = 0; i < 2; i++) {
        int idx = i * 256 + tid;
        int row = idx >> 2, grp = idx & 3;
        pbh[i] = *(const uint4*)(Wh1 + (size_t)row * 256 + grp * 8);
        pbl[i] = *(const uint4*)(Wl1 + (size_t)row * 256 + grp * 8);
    }

    for (int kc = 0; kc < NCHUNK; kc++) {
        // ---- store staged chunk to smem (A converted fp32 -> hi/lo) ----
#pragma unroll
        for (int i = 0; i < 4; i++) {
            int r = aR + i * 32;
            float4 v = pa[i];
            __nv_bfloat162 h01 = __floats2bfloat162_rn(v.x, v.y);
            __nv_bfloat162 h23 = __floats2bfloat162_rn(v.z, v.w);
            float l0 = v.x - __bfloat162float(h01.x);
            float l1 = v.y - __bfloat162float(h01.y);
            float l2 = v.z - __bfloat162float(h23.x);
            float l3 = v.w - __bfloat162float(h23.y);
            *(uint2*)((char*)sAhi + r * (PITCH * 2) + aKg * 8) =
                make_uint2(*(uint32_t*)&h01, *(uint32_t*)&h23);
            *(uint2*)((char*)sAlo + r * (PITCH * 2) + aKg * 8) =
                make_uint2(pack_bf2(l0, l1), pack_bf2(l2, l3));
        }
#pragma unroll
        for (int i = 0; i < 2; i++) {
            int idx = i * 256 + tid;
            int row = idx >> 2, grp = idx & 3;
            *(uint4*)((char*)sBhi + row * (PITCH * 2) + grp * 16) = pbh[i];
            *(uint4*)((char*)sBlo + row * (PITCH * 2) + grp * 16) = pbl[i];
        }
        __syncthreads();

        // ---- prefetch next chunk ----
        if (kc + 1 < NCHUNK) {
            int kn = kc + 1;
            const float* Ap = (DUAL && kn >= 8) ? Ab2 + (kn - 8) * 32 : Ab1 + kn * 32;
            const __nv_bfloat16* Whp = (DUAL && kn >= 8) ? Wh2 + (kn - 8) * 32 : Wh1 + kn * 32;
            const __nv_bfloat16* Wlp = (DUAL && kn >= 8) ? Wl2 + (kn - 8) * 32 : Wl1 + kn * 32;
#pragma unroll
            for (int i = 0; i < 4; i++)
                pa[i] = *(const float4*)&Ap[(size_t)(aR + i * 32) * 256 + aKg * 4];
#pragma unroll
            for (int i = 0; i < 2; i++) {
                int idx = i * 256 + tid;
                int row = idx >> 2, grp = idx & 3;
                pbh[i] = *(const uint4*)(Whp + (size_t)row * 256 + grp * 8);
                pbl[i] = *(const uint4*)(Wlp + (size_t)row * 256 + grp * 8);
            }
        }

        // ---- compute 2 k-steps of 16 ----
#pragma unroll
        for (int ks = 0; ks < 2; ks++) {
            const uint32_t kso = ks * 32;
            uint32_t ah[4][4], al[4][4];
#pragma unroll
            for (int mi = 0; mi < 4; mi++) {
                ldsm_x4(ah[mi], aHiB + kso + mi * 16 * (PITCH * 2));
                ldsm_x4(al[mi], aLoB + kso + mi * 16 * (PITCH * 2));
            }
            uint32_t bh[2][4], bl[2][4];
#pragma unroll
            for (int n2 = 0; n2 < 2; n2++) {
                ldsm_x4(bh[n2], bHiB + kso + n2 * 16 * (PITCH * 2));
                ldsm_x4(bl[n2], bLoB + kso + n2 * 16 * (PITCH * 2));
            }
#pragma unroll
            for (int mi = 0; mi < 4; mi++)
#pragma unroll
                for (int ni = 0; ni < 4; ni++) {
                    int n2 = ni >> 1, j = (ni & 1) * 2;
                    mma_bf16(c[mi][ni], ah[mi], bh[n2][j], bh[n2][j + 1]);
                    mma_bf16(c[mi][ni], ah[mi], bl[n2][j], bl[n2][j + 1]);
                    mma_bf16(c[mi][ni], al[mi], bh[n2][j], bh[n2][j + 1]);
                }
        }
        __syncthreads();
    }

    // ---- epilogue ----
#pragma unroll
    for (int mi = 0; mi < 4; mi++) {
        int row0 = rowBase + warpM * 64 + mi * 16 + (lane >> 2);
#pragma unroll
        for (int ni = 0; ni < 4; ni++) {
            int col = colBase + warpN * 32 + ni * 8 + (lane & 3) * 2;
            float b0 = bias1[col], b1 = bias1[col + 1];
            if (EPI == 2) { b0 += bias2[col]; b1 += bias2[col + 1]; }
#pragma unroll
            for (int half = 0; half < 2; half++) {
                int row = row0 + half * 8;
                float v0 = c[mi][ni][half * 2 + 0] + b0;
                float v1 = c[mi][ni][half * 2 + 1] + b1;
                if (EPI >= 1) { v0 = gelu_exact(v0); v1 = gelu_exact(v1); }
                if (EPI == 2) {
                    float2 rs = *(const float2*)&resid[(size_t)row * Nn + col];
                    v0 += rs.x; v1 += rs.y;
                }
                *(float2*)&C[(size_t)row * Nn + col] = make_float2(v0, v1);
            }
        }
    }
}

// ---------------- Householder ----------------
__device__ __forceinline__ void build_Q(float p0, float p1, float p2, float p3,
                                        float p4, float p5, float Q[4][4]) {
#pragma unroll
    for (int i = 0; i < 4; i++)
#pragma unroll
        for (int j = 0; j < 4; j++) Q[i][j] = (i == j) ? 1.f : 0.f;
    {
        float inv = 2.f / (1.f + p0 * p0 + p1 * p1 + p2 * p2);
#pragma unroll
        for (int i = 0; i < 4; i++) {
            float qv = Q[i][0] + Q[i][1] * p0 + Q[i][2] * p1 + Q[i][3] * p2;
            float s = inv * qv;
            Q[i][0] -= s; Q[i][1] -= s * p0; Q[i][2] -= s * p1; Q[i][3] -= s * p2;
        }
    }
    {
        float inv = 2.f / (1.f + p3 * p3 + p4 * p4);
#pragma unroll
        for (int i = 0; i < 4; i++) {
            float qv = Q[i][1] + Q[i][2] * p3 + Q[i][3] * p4;
            float s = inv * qv;
            Q[i][1] -= s; Q[i][2] -= s * p3; Q[i][3] -= s * p4;
        }
    }
    {
        float inv = 2.f / (1.f + p5 * p5);
#pragma unroll
        for (int i = 0; i < 4; i++) {
            float qv = Q[i][2] + Q[i][3] * p5;
            float s = inv * qv;
            Q[i][2] -= s; Q[i][3] -= s * p5;
        }
    }
}

// ---------------- Householder Q + forward bundle rotate --------------------
__global__ void hh_kernel(const float* __restrict__ rep, const float* __restrict__ x,
                          float* __restrict__ hv) {
    int t = blockIdx.x * blockDim.x + threadIdx.x;
    if (t >= NN * NB) return;
    int n = t >> 6;
    int b = t & 63;
    const float* p = rep + (size_t)n * NBP + b * 6;
    float Q[4][4];
    build_Q(p[0], p[1], p[2], p[3], p[4], p[5], Q);
    float4 xv = *(const float4*)&x[(size_t)n * CH + b * 4];
    float xr[4] = {xv.x, xv.y, xv.z, xv.w};
    float4 ov; float* o = &ov.x;
#pragma unroll
    for (int cc = 0; cc < 4; cc++)
        o[cc] = Q[cc][0] * xr[0] + Q[cc][1] * xr[1] + Q[cc][2] * xr[2] + Q[cc][3] * xr[3];
    *(float4*)&hv[(size_t)n * CH + b * 4] = ov;
}

// ---------------- spectral projection ----------------
__global__ void spec_fwd(const float* __restrict__ ev, const float* __restrict__ hv,
                         const float* __restrict__ eigval, const float* __restrict__ taus,
                         float* __restrict__ hs) {
    const int g = blockIdx.x;
    const int cc = blockIdx.y * 128 + threadIdx.x;
    const int gbase = g * NPG;
    __shared__ float evs[8][KEIG];
    float acc[KEIG];
#pragma unroll
    for (int k = 0; k < KEIG; k++) acc[k] = 0.f;
    for (int n0 = 0; n0 < NPG; n0 += 8) {
        __syncthreads();
        for (int i = threadIdx.x; i < 8 * KEIG; i += 128) {
            int r = i >> 5, kk = i & 31;
            evs[r][kk] = ev[(size_t)(gbase + n0 + r) * KEIG + kk];
        }
        __syncthreads();
#pragma unroll
        for (int r = 0; r < 8; r++) {
            float hval = hv[(size_t)(gbase + n0 + r) * CH + cc];
#pragma unroll
            for (int k = 0; k < KEIG; k++) acc[k] += evs[r][k] * hval;
        }
    }
    float tau = taus[cc >> 2];
#pragma unroll
    for (int k = 0; k < KEIG; k++) {
        float f = expf(-eigval[g * KEIG + k] * tau);
        hs[(size_t)(g * KEIG + k) * CH + cc] = acc[k] * f;
    }
}

// ---------------- spectral reprojection ----------------
__global__ void spec_bwd(const float* __restrict__ ev, const float* __restrict__ hs,
                         float* __restrict__ out) {
    const int g = blockIdx.x;
    const int nbase = g * NPG + blockIdx.y * 64;
    __shared__ float hss[KEIG][CH];
    __shared__ float evs[64][KEIG];
    for (int i = 0; i < KEIG; i++)
        hss[i][threadIdx.x] = hs[(size_t)(g * KEIG + i) * CH + threadIdx.x];
    for (int i = threadIdx.x; i < 64 * KEIG; i += 256) {
        int r = i >> 5, kk = i & 31;
        evs[r][kk] = ev[(size_t)(nbase + r) * KEIG + kk];
    }
    __syncthreads();
    for (int r = 0; r < 64; r++) {
        float s = 0.f;
#pragma unroll
        for (int k = 0; k < KEIG; k++) s += evs[r][k] * hss[k][threadIdx.x];
        out[(size_t)(nbase + r) * CH + threadIdx.x] = s;
    }
}

// ---------------- final: out = Q^T @ hl ----------------
__global__ void final_kernel(const float* __restrict__ rep,
                             const float* __restrict__ hl,
                             float* __restrict__ out) {
    int t = blockIdx.x * blockDim.x + threadIdx.x;
    if (t >= NN * NB) return;
    int n = t >> 6;
    int b = t & 63;
    const float* p = rep + (size_t)n * NBP + b * 6;
    float Q[4][4];
    build_Q(p[0], p[1], p[2], p[3], p[4], p[5], Q);
    float4 hvv = *(const float4*)&hl[(size_t)n * CH + b * 4];
    float hr[4] = {hvv.x, hvv.y, hvv.z, hvv.w};
    float4 ov; float* o = &ov.x;
#pragma unroll
    for (int cc = 0; cc < 4; cc++)
        o[cc] = Q[0][cc] * hr[0] + Q[1][cc] * hr[1] + Q[2][cc] * hr[2] + Q[3][cc] * hr[3];
    *(float4*)&out[(size_t)n * CH + b * 4] = ov;
}

// ---------------- orchestration ----------------
extern "C" void kernel_launch(void* const* d_in, const int* in_sizes, int n_in,
                              void* d_out, int out_size) {
    const float* x      = (const float*)d_in[0];
    const float* eigvec = (const float*)d_in[1];
    const float* eigval = (const float*)d_in[2];
    const float* taus   = (const float*)d_in[3];
    const float* enc_w  = (const float*)d_in[4];
    const float* enc_b  = (const float*)d_in[5];
    const float* self_w = (const float*)d_in[6];
    const float* self_b = (const float*)d_in[7];
    const float* nb_w   = (const float*)d_in[8];
    const float* nb_b   = (const float*)d_in[9];
    const float* dec_w  = (const float*)d_in[10];
    const float* dec_b  = (const float*)d_in[11];
    const float* lin_w  = (const float*)d_in[12];
    const float* lin_b  = (const float*)d_in[13];
    const int*   ei     = (const int*)d_in[14];
    float* out = (float*)d_out;

    const int E = in_sizes[14] / 2;

    float *h, *tmp, *agg, *rep, *hs;
    __nv_bfloat16 *whi, *wlo;
    cudaGetSymbolAddress((void**)&h,   g_h);
    cudaGetSymbolAddress((void**)&tmp, g_tmp);
    cudaGetSymbolAddress((void**)&agg, g_agg);
    cudaGetSymbolAddress((void**)&rep, g_rep);
    cudaGetSymbolAddress((void**)&hs,  g_hs);
    cudaGetSymbolAddress((void**)&whi, g_whi);
    cudaGetSymbolAddress((void**)&wlo, g_wlo);
    float* agg2 = rep;   // rep buffer (96MB) doubles as layer-1 agg scratch

    // launch 0: weight convert
    convert_all<<<(WTOT + 255) / 256, 256>>>(enc_w, self_w, nb_w, dec_w, lin_w, whi, wlo);
    // launches 1,2: zero both agg buffers up-front
    cudaMemsetAsync(agg,  0, (size_t)NN * CH * sizeof(float));
    cudaMemsetAsync(agg2, 0, (size_t)NN * CH * sizeof(float));

    dim3 gemm_grid(CH / 128, NN / 128);   // (2, 512)
    dim3 dec_grid(NBP / 128, NN / 128);   // (3, 512)

    // launch 3: h = gelu(x @ enc_w + enc_b)
    tgemm<1, 0><<<gemm_grid, 256>>>(x, nullptr, whi + OFF_ENC, wlo + OFF_ENC,
                                    nullptr, nullptr, enc_b, nullptr, nullptr, h, CH);

    // layer 0: launch 4 scatter, launch 5 dual-GEMM (ncu -s 5 lands here)
    scatter_kernel<<<(int)(((long)E * 64 + 255) / 256), 256>>>(h, ei, agg, E);
    tgemm<2, 1><<<gemm_grid, 256>>>(h, agg,
                                    whi + OFF_SELF0, wlo + OFF_SELF0,
                                    whi + OFF_NB0,   wlo + OFF_NB0,
                                    self_b, nb_b, h, tmp, CH);

    // layer 1
    scatter_kernel<<<(int)(((long)E * 64 + 255) / 256), 256>>>(tmp, ei, agg2, E);
    tgemm<2, 1><<<gemm_grid, 256>>>(tmp, agg2,
                                    whi + OFF_SELF1, wlo + OFF_SELF1,
                                    whi + OFF_NB1,   wlo + OFF_NB1,
                                    self_b + CH, nb_b + CH, tmp, h, CH);

    // node_rep = h @ dec_w + dec_b   (overwrites agg2 scratch — safe, consumed)
    tgemm<0, 0><<<dec_grid, 256>>>(h, nullptr, whi + OFF_DEC, wlo + OFF_DEC,
                                   nullptr, nullptr, dec_b, nullptr, nullptr, rep, NBP);

    // Householder Q + forward rotate (hv into tmp)
    hh_kernel<<<NN * NB / 256, 256>>>(rep, x, tmp);

    // spectral filter (hv in tmp; output into h)
    spec_fwd<<<dim3(GG, 2), 128>>>(eigvec, tmp, eigval, taus, hs);
    spec_bwd<<<dim3(GG, NPG / 64), 256>>>(eigvec, hs, h);

    // hl = spec_out @ lin_w + lin_b  (into tmp)
    tgemm<0, 0><<<gemm_grid, 256>>>(h, nullptr, whi + OFF_LIN, wlo + OFF_LIN,
                                    nullptr, nullptr, lin_b, nullptr, nullptr, tmp, CH);

    // out = Q^T @ hl
    final_kernel<<<NN * NB / 256, 256>>>(rep, tmp, out);
}

// round 9
// speedup vs baseline: 1.0394x; 1.0394x over previous
#include <cuda_runtime.h>
#include <cuda_bf16.h>
#include <math.h>
#include <stdint.h>

// ---------------- problem constants ----------------
#define NN      65536
#define CH      256      // IN_CH == GNN_DIM
#define GG      64
#define NPG     1024
#define KEIG    32
#define NB      64
#define BD      4
#define NBP     384
#define LAYERS  2

#define WTOT    491520
#define OFF_ENC   0
#define OFF_SELF0 65536
#define OFF_SELF1 131072
#define OFF_NB0   196608
#define OFF_NB1   262144
#define OFF_DEC   327680
#define OFF_LIN   425984

// ---------------- scratch (device globals; no mallocs allowed) -------------
__device__ float g_h  [NN * CH];
__device__ float g_tmp[NN * CH];
__device__ float g_agg[NN * CH];
__device__ float g_rep[NN * NBP];   // also used as agg scratch for layer 1
__device__ float g_hs [GG * KEIG * CH];
__device__ __nv_bfloat16 g_whi[WTOT];
__device__ __nv_bfloat16 g_wlo[WTOT];

__device__ __forceinline__ float gelu_exact(float x) {
    return 0.5f * x * (1.0f + erff(x * 0.7071067811865476f));
}
__device__ __forceinline__ uint32_t pack_bf2(float a, float b) {
    __nv_bfloat162 t = __floats2bfloat162_rn(a, b);
    return *(uint32_t*)&t;
}
__device__ __forceinline__ uint32_t smem_u32(const void* p) {
    uint32_t a;
    asm("{ .reg .u64 t; cvta.to.shared.u64 t, %1; cvt.u32.u64 %0, t; }" : "=r"(a) : "l"(p));
    return a;
}
__device__ __forceinline__ void ldsm_x4(uint32_t* r, uint32_t addr) {
    asm volatile("ldmatrix.sync.aligned.m8n8.x4.shared.b16 {%0,%1,%2,%3}, [%4];"
                 : "=r"(r[0]), "=r"(r[1]), "=r"(r[2]), "=r"(r[3]) : "r"(addr));
}
__device__ __forceinline__ void mma_bf16(float* c, const uint32_t* a, uint32_t b0, uint32_t b1) {
    asm volatile("mma.sync.aligned.m16n8k16.row.col.f32.bf16.bf16.f32 "
                 "{%0,%1,%2,%3}, {%4,%5,%6,%7}, {%8,%9}, {%0,%1,%2,%3};"
                 : "+f"(c[0]), "+f"(c[1]), "+f"(c[2]), "+f"(c[3])
                 : "r"(a[0]), "r"(a[1]), "r"(a[2]), "r"(a[3]), "r"(b0), "r"(b1));
}

// ---------------- fused weight convert+transpose (single launch) -----------
__global__ void convert_all(const float* __restrict__ enc, const float* __restrict__ selfw,
                            const float* __restrict__ nbw, const float* __restrict__ dec,
                            const float* __restrict__ lin,
                            __nv_bfloat16* __restrict__ dhi,
                            __nv_bfloat16* __restrict__ dlo) {
    int t = blockIdx.x * blockDim.x + threadIdx.x;
    if (t >= WTOT) return;
    const float* src;
    int local, Ncols, dstoff;
    if (t < OFF_SELF0)      { src = enc;            local = t;              Ncols = 256; dstoff = OFF_ENC; }
    else if (t < OFF_SELF1) { src = selfw;          local = t - OFF_SELF0;  Ncols = 256; dstoff = OFF_SELF0; }
    else if (t < OFF_NB0)   { src = selfw + 65536;  local = t - OFF_SELF1;  Ncols = 256; dstoff = OFF_SELF1; }
    else if (t < OFF_NB1)   { src = nbw;            local = t - OFF_NB0;    Ncols = 256; dstoff = OFF_NB0; }
    else if (t < OFF_DEC)   { src = nbw + 65536;    local = t - OFF_NB1;    Ncols = 256; dstoff = OFF_NB1; }
    else if (t < OFF_LIN)   { src = dec;            local = t - OFF_DEC;    Ncols = 384; dstoff = OFF_DEC; }
    else                    { src = lin;            local = t - OFF_LIN;    Ncols = 256; dstoff = OFF_LIN; }
    int k = local / Ncols, n = local % Ncols;
    float v = src[local];
    __nv_bfloat16 h = __float2bfloat16_rn(v);
    dhi[dstoff + (size_t)n * 256 + k] = h;
    dlo[dstoff + (size_t)n * 256 + k] = __float2bfloat16_rn(v - __bfloat162float(h));
}

// ---------------- edge scatter: agg[dst] += h[src] (vector red atomics) ----
__global__ void scatter_kernel(const float* __restrict__ h,
                               const int* __restrict__ ei,
                               float* __restrict__ agg, int E) {
    long t = (long)blockIdx.x * blockDim.x + threadIdx.x;
    if (t >= (long)E * 64) return;
    int e = (int)(t >> 6);
    int q = (int)(t & 63);
    int s = ei[e];
    int d = ei[E + e];
    float4 v = ((const float4*)(h + (size_t)s * CH))[q];
    float* dst = agg + (size_t)d * CH + q * 4;
    asm volatile("red.global.add.v4.f32 [%0], {%1, %2, %3, %4};"
                 :: "l"(dst), "f"(v.x), "f"(v.y), "f"(v.z), "f"(v.w)
                 : "memory");
}

// ---------------- HMMA GEMM, double-buffered smem --------------------------
// CTA tile 128x64, warp tile 32x32 (warps 4x2), K chunks of 32, 2 CTAs/SM.
// Split product: D = Ahi*Whi + Ahi*Wlo + Alo*Whi (fp32 accum).
// EPI 0: C = acc + bias1 ; EPI 1: gelu ; EPI 2 (DUAL): gelu(acc+b1+b2)+resid
#define PITCH 40          // bf16 per smem row (80 B) -> conflict-free ldmatrix
#define SM_AHI 0          // 128*40*2B = 10240
#define SM_ALO 10240
#define SM_BHI 20480      //  64*40*2B = 5120
#define SM_BLO 25600
#define SM_BUF 30720      // bytes per buffer
#define SM_TOT 61440      // 2 buffers

template <int EPI, int DUAL>
__global__ void __launch_bounds__(256, 2)
tgemm(const float* __restrict__ A1, const float* __restrict__ A2,
      const __nv_bfloat16* __restrict__ W1hi, const __nv_bfloat16* __restrict__ W1lo,
      const __nv_bfloat16* __restrict__ W2hi, const __nv_bfloat16* __restrict__ W2lo,
      const float* __restrict__ bias1, const float* __restrict__ bias2,
      const float* __restrict__ resid,
      float* __restrict__ C, int Nn) {
    extern __shared__ __align__(16) char smem[];

    const int tid  = threadIdx.x;
    const int lane = tid & 31;
    const int wid  = tid >> 5;
    const int warpM = wid & 3;     // 4 warps over M (32 rows)
    const int warpN = wid >> 2;    // 2 warps over N (32 cols)
    const int rowBase = blockIdx.y * 128;
    const int colBase = blockIdx.x * 64;

    const float* Ab1 = A1 + (size_t)rowBase * 256;
    const float* Ab2 = DUAL ? A2 + (size_t)rowBase * 256 : nullptr;
    const __nv_bfloat16* Wh1 = W1hi + (size_t)colBase * 256;
    const __nv_bfloat16* Wl1 = W1lo + (size_t)colBase * 256;
    const __nv_bfloat16* Wh2 = DUAL ? W2hi + (size_t)colBase * 256 : nullptr;
    const __nv_bfloat16* Wl2 = DUAL ? W2lo + (size_t)colBase * 256 : nullptr;

    // hoisted ldmatrix fragment offsets
    const uint32_t aFragOff = (uint32_t)(warpM * 32 + (lane & 15)) * (PITCH * 2)
                              + (lane >> 4) * 16;
    const int g = lane >> 3, lr = lane & 7;
    const uint32_t bFragOff = (uint32_t)(warpN * 32 + ((g >> 1) << 3) + lr) * (PITCH * 2)
                              + (g & 1) * 16;
    const uint32_t smemBase = smem_u32(smem);

    float c[2][4][4];
#pragma unroll
    for (int mi = 0; mi < 2; mi++)
#pragma unroll
        for (int ni = 0; ni < 4; ni++)
#pragma unroll
            for (int e = 0; e < 4; e++) c[mi][ni][e] = 0.f;

    // staging coords
    const int aR = tid >> 3;        // + i*32
    const int aKg = tid & 7;
    const int bR = tid >> 2;
    const int bKg = tid & 3;

    const int NCHUNK = DUAL ? 16 : 8;

    float4 pa[4];
    uint4  pbh, pbl;

    auto prefetch = [&](int kn) {
        const float* Ap = (DUAL && kn >= 8) ? Ab2 + (kn - 8) * 32 : Ab1 + kn * 32;
        const __nv_bfloat16* Whp = (DUAL && kn >= 8) ? Wh2 + (kn - 8) * 32 : Wh1 + kn * 32;
        const __nv_bfloat16* Wlp = (DUAL && kn >= 8) ? Wl2 + (kn - 8) * 32 : Wl1 + kn * 32;
#pragma unroll
        for (int i = 0; i < 4; i++)
            pa[i] = *(const float4*)&Ap[(size_t)(aR + i * 32) * 256 + aKg * 4];
        pbh = *(const uint4*)(Whp + (size_t)bR * 256 + bKg * 8);
        pbl = *(const uint4*)(Wlp + (size_t)bR * 256 + bKg * 8);
    };
    auto stage = [&](int buf) {
        char* base = smem + buf * SM_BUF;
#pragma unroll
        for (int i = 0; i < 4; i++) {
            int r = aR + i * 32;
            float4 v = pa[i];
            __nv_bfloat162 h01 = __floats2bfloat162_rn(v.x, v.y);
            __nv_bfloat162 h23 = __floats2bfloat162_rn(v.z, v.w);
            float l0 = v.x - __bfloat162float(h01.x);
            float l1 = v.y - __bfloat162float(h01.y);
            float l2 = v.z - __bfloat162float(h23.x);
            float l3 = v.w - __bfloat162float(h23.y);
            *(uint2*)(base + SM_AHI + r * (PITCH * 2) + aKg * 8) =
                make_uint2(*(uint32_t*)&h01, *(uint32_t*)&h23);
            *(uint2*)(base + SM_ALO + r * (PITCH * 2) + aKg * 8) =
                make_uint2(pack_bf2(l0, l1), pack_bf2(l2, l3));
        }
        *(uint4*)(base + SM_BHI + bR * (PITCH * 2) + bKg * 16) = pbh;
        *(uint4*)(base + SM_BLO + bR * (PITCH * 2) + bKg * 16) = pbl;
    };

    prefetch(0);
    stage(0);
    __syncthreads();
    if (NCHUNK > 1) prefetch(1);

    for (int kc = 0; kc < NCHUNK; kc++) {
        if (kc + 1 < NCHUNK) stage((kc + 1) & 1);
        if (kc + 2 < NCHUNK) prefetch(kc + 2);

        const uint32_t bufOff = smemBase + (kc & 1) * SM_BUF;
        const uint32_t aHiB = bufOff + SM_AHI + aFragOff;
        const uint32_t aLoB = bufOff + SM_ALO + aFragOff;
        const uint32_t bHiB = bufOff + SM_BHI + bFragOff;
        const uint32_t bLoB = bufOff + SM_BLO + bFragOff;

#pragma unroll
        for (int ks = 0; ks < 2; ks++) {
            const uint32_t kso = ks * 32;
            uint32_t ah[2][4], al[2][4];
#pragma unroll
            for (int mi = 0; mi < 2; mi++) {
                ldsm_x4(ah[mi], aHiB + kso + mi * 16 * (PITCH * 2));
                ldsm_x4(al[mi], aLoB + kso + mi * 16 * (PITCH * 2));
            }
            uint32_t bh[2][4], bl[2][4];
#pragma unroll
            for (int n2 = 0; n2 < 2; n2++) {
                ldsm_x4(bh[n2], bHiB + kso + n2 * 16 * (PITCH * 2));
                ldsm_x4(bl[n2], bLoB + kso + n2 * 16 * (PITCH * 2));
            }
#pragma unroll
            for (int mi = 0; mi < 2; mi++)
#pragma unroll
                for (int ni = 0; ni < 4; ni++) {
                    int n2 = ni >> 1, j = (ni & 1) * 2;
                    mma_bf16(c[mi][ni], ah[mi], bh[n2][j], bh[n2][j + 1]);
                    mma_bf16(c[mi][ni], ah[mi], bl[n2][j], bl[n2][j + 1]);
                    mma_bf16(c[mi][ni], al[mi], bh[n2][j], bh[n2][j + 1]);
                }
        }
        __syncthreads();
    }

    // ---- epilogue ----
#pragma unroll
    for (int mi = 0; mi < 2; mi++) {
        int row0 = rowBase + warpM * 32 + mi * 16 + (lane >> 2);
#pragma unroll
        for (int ni = 0; ni < 4; ni++) {
            int col = colBase + warpN * 32 + ni * 8 + (lane & 3) * 2;
            float b0 = bias1[col], b1 = bias1[col + 1];
            if (EPI == 2) { b0 += bias2[col]; b1 += bias2[col + 1]; }
#pragma unroll
            for (int half = 0; half < 2; half++) {
                int row = row0 + half * 8;
                float v0 = c[mi][ni][half * 2 + 0] + b0;
                float v1 = c[mi][ni][half * 2 + 1] + b1;
                if (EPI >= 1) { v0 = gelu_exact(v0); v1 = gelu_exact(v1); }
                if (EPI == 2) {
                    float2 rs = *(const float2*)&resid[(size_t)row * Nn + col];
                    v0 += rs.x; v1 += rs.y;
                }
                *(float2*)&C[(size_t)row * Nn + col] = make_float2(v0, v1);
            }
        }
    }
}

// ---------------- Householder ----------------
__device__ __forceinline__ void build_Q(float p0, float p1, float p2, float p3,
                                        float p4, float p5, float Q[4][4]) {
#pragma unroll
    for (int i = 0; i < 4; i++)
#pragma unroll
        for (int j = 0; j < 4; j++) Q[i][j] = (i == j) ? 1.f : 0.f;
    {
        float inv = 2.f / (1.f + p0 * p0 + p1 * p1 + p2 * p2);
#pragma unroll
        for (int i = 0; i < 4; i++) {
            float qv = Q[i][0] + Q[i][1] * p0 + Q[i][2] * p1 + Q[i][3] * p2;
            float s = inv * qv;
            Q[i][0] -= s; Q[i][1] -= s * p0; Q[i][2] -= s * p1; Q[i][3] -= s * p2;
        }
    }
    {
        float inv = 2.f / (1.f + p3 * p3 + p4 * p4);
#pragma unroll
        for (int i = 0; i < 4; i++) {
            float qv = Q[i][1] + Q[i][2] * p3 + Q[i][3] * p4;
            float s = inv * qv;
            Q[i][1] -= s; Q[i][2] -= s * p3; Q[i][3] -= s * p4;
        }
    }
    {
        float inv = 2.f / (1.f + p5 * p5);
#pragma unroll
        for (int i = 0; i < 4; i++) {
            float qv = Q[i][2] + Q[i][3] * p5;
            float s = inv * qv;
            Q[i][2] -= s; Q[i][3] -= s * p5;
        }
    }
}

// ---------------- Householder Q + forward bundle rotate --------------------
__global__ void hh_kernel(const float* __restrict__ rep, const float* __restrict__ x,
                          float* __restrict__ hv) {
    int t = blockIdx.x * blockDim.x + threadIdx.x;
    if (t >= NN * NB) return;
    int n = t >> 6;
    int b = t & 63;
    const float* p = rep + (size_t)n * NBP + b * 6;
    float Q[4][4];
    build_Q(p[0], p[1], p[2], p[3], p[4], p[5], Q);
    float4 xv = *(const float4*)&x[(size_t)n * CH + b * 4];
    float xr[4] = {xv.x, xv.y, xv.z, xv.w};
    float4 ov; float* o = &ov.x;
#pragma unroll
    for (int cc = 0; cc < 4; cc++)
        o[cc] = Q[cc][0] * xr[0] + Q[cc][1] * xr[1] + Q[cc][2] * xr[2] + Q[cc][3] * xr[3];
    *(float4*)&hv[(size_t)n * CH + b * 4] = ov;
}

// ---------------- spectral projection ----------------
__global__ void spec_fwd(const float* __restrict__ ev, const float* __restrict__ hv,
                         const float* __restrict__ eigval, const float* __restrict__ taus,
                         float* __restrict__ hs) {
    const int g = blockIdx.x;
    const int cc = blockIdx.y * 128 + threadIdx.x;
    const int gbase = g * NPG;
    __shared__ float evs[8][KEIG];
    float acc[KEIG];
#pragma unroll
    for (int k = 0; k < KEIG; k++) acc[k] = 0.f;
    for (int n0 = 0; n0 < NPG; n0 += 8) {
        __syncthreads();
        for (int i = threadIdx.x; i < 8 * KEIG; i += 128) {
            int r = i >> 5, kk = i & 31;
            evs[r][kk] = ev[(size_t)(gbase + n0 + r) * KEIG + kk];
        }
        __syncthreads();
#pragma unroll
        for (int r = 0; r < 8; r++) {
            float hval = hv[(size_t)(gbase + n0 + r) * CH + cc];
#pragma unroll
            for (int k = 0; k < KEIG; k++) acc[k] += evs[r][k] * hval;
        }
    }
    float tau = taus[cc >> 2];
#pragma unroll
    for (int k = 0; k < KEIG; k++) {
        float f = expf(-eigval[g * KEIG + k] * tau);
        hs[(size_t)(g * KEIG + k) * CH + cc] = acc[k] * f;
    }
}

// ---------------- spectral reprojection ----------------
__global__ void spec_bwd(const float* __restrict__ ev, const float* __restrict__ hs,
                         float* __restrict__ out) {
    const int g = blockIdx.x;
    const int nbase = g * NPG + blockIdx.y * 64;
    __shared__ float hss[KEIG][CH];
    __shared__ float evs[64][KEIG];
    for (int i = 0; i < KEIG; i++)
        hss[i][threadIdx.x] = hs[(size_t)(g * KEIG + i) * CH + threadIdx.x];
    for (int i = threadIdx.x; i < 64 * KEIG; i += 256) {
        int r = i >> 5, kk = i & 31;
        evs[r][kk] = ev[(size_t)(nbase + r) * KEIG + kk];
    }
    __syncthreads();
    for (int r = 0; r < 64; r++) {
        float s = 0.f;
#pragma unroll
        for (int k = 0; k < KEIG; k++) s += evs[r][k] * hss[k][threadIdx.x];
        out[(size_t)(nbase + r) * CH + threadIdx.x] = s;
    }
}

// ---------------- final: out = Q^T @ hl ----------------
__global__ void final_kernel(const float* __restrict__ rep,
                             const float* __restrict__ hl,
                             float* __restrict__ out) {
    int t = blockIdx.x * blockDim.x + threadIdx.x;
    if (t >= NN * NB) return;
    int n = t >> 6;
    int b = t & 63;
    const float* p = rep + (size_t)n * NBP + b * 6;
    float Q[4][4];
    build_Q(p[0], p[1], p[2], p[3], p[4], p[5], Q);
    float4 hvv = *(const float4*)&hl[(size_t)n * CH + b * 4];
    float hr[4] = {hvv.x, hvv.y, hvv.z, hvv.w};
    float4 ov; float* o = &ov.x;
#pragma unroll
    for (int cc = 0; cc < 4; cc++)
        o[cc] = Q[0][cc] * hr[0] + Q[1][cc] * hr[1] + Q[2][cc] * hr[2] + Q[3][cc] * hr[3];
    *(float4*)&out[(size_t)n * CH + b * 4] = ov;
}

// ---------------- orchestration ----------------
extern "C" void kernel_launch(void* const* d_in, const int* in_sizes, int n_in,
                              void* d_out, int out_size) {
    const float* x      = (const float*)d_in[0];
    const float* eigvec = (const float*)d_in[1];
    const float* eigval = (const float*)d_in[2];
    const float* taus   = (const float*)d_in[3];
    const float* enc_w  = (const float*)d_in[4];
    const float* enc_b  = (const float*)d_in[5];
    const float* self_w = (const float*)d_in[6];
    const float* self_b = (const float*)d_in[7];
    const float* nb_w   = (const float*)d_in[8];
    const float* nb_b   = (const float*)d_in[9];
    const float* dec_w  = (const float*)d_in[10];
    const float* dec_b  = (const float*)d_in[11];
    const float* lin_w  = (const float*)d_in[12];
    const float* lin_b  = (const float*)d_in[13];
    const int*   ei     = (const int*)d_in[14];
    float* out = (float*)d_out;

    const int E = in_sizes[14] / 2;

    float *h, *tmp, *agg, *rep, *hs;
    __nv_bfloat16 *whi, *wlo;
    cudaGetSymbolAddress((void**)&h,   g_h);
    cudaGetSymbolAddress((void**)&tmp, g_tmp);
    cudaGetSymbolAddress((void**)&agg, g_agg);
    cudaGetSymbolAddress((void**)&rep, g_rep);
    cudaGetSymbolAddress((void**)&hs,  g_hs);
    cudaGetSymbolAddress((void**)&whi, g_whi);
    cudaGetSymbolAddress((void**)&wlo, g_wlo);
    float* agg2 = rep;   // rep buffer (96MB) doubles as layer-1 agg scratch

    cudaFuncSetAttribute(tgemm<0, 0>, cudaFuncAttributeMaxDynamicSharedMemorySize, SM_TOT);
    cudaFuncSetAttribute(tgemm<1, 0>, cudaFuncAttributeMaxDynamicSharedMemorySize, SM_TOT);
    cudaFuncSetAttribute(tgemm<2, 1>, cudaFuncAttributeMaxDynamicSharedMemorySize, SM_TOT);

    // launch 0: weight convert
    convert_all<<<(WTOT + 255) / 256, 256>>>(enc_w, self_w, nb_w, dec_w, lin_w, whi, wlo);
    // launches 1,2: zero both agg buffers up-front
    cudaMemsetAsync(agg,  0, (size_t)NN * CH * sizeof(float));
    cudaMemsetAsync(agg2, 0, (size_t)NN * CH * sizeof(float));

    dim3 gemm_grid(CH / 64, NN / 128);   // (4, 512)
    dim3 dec_grid(NBP / 64, NN / 128);   // (6, 512)

    // launch 3: h = gelu(x @ enc_w + enc_b)
    tgemm<1, 0><<<gemm_grid, 256, SM_TOT>>>(x, nullptr, whi + OFF_ENC, wlo + OFF_ENC,
                                            nullptr, nullptr, enc_b, nullptr, nullptr, h, CH);

    // layer 0: launch 4 scatter, launch 5 dual-GEMM (ncu -s 5 lands here)
    scatter_kernel<<<(int)(((long)E * 64 + 255) / 256), 256>>>(h, ei, agg, E);
    tgemm<2, 1><<<gemm_grid, 256, SM_TOT>>>(h, agg,
                                            whi + OFF_SELF0, wlo + OFF_SELF0,
                                            whi + OFF_NB0,   wlo + OFF_NB0,
                                            self_b, nb_b, h, tmp, CH);

    // layer 1
    scatter_kernel<<<(int)(((long)E * 64 + 255) / 256), 256>>>(tmp, ei, agg2, E);
    tgemm<2, 1><<<gemm_grid, 256, SM_TOT>>>(tmp, agg2,
                                            whi + OFF_SELF1, wlo + OFF_SELF1,
                                            whi + OFF_NB1,   wlo + OFF_NB1,
                                            self_b + CH, nb_b + CH, tmp, h, CH);

    // node_rep = h @ dec_w + dec_b   (overwrites agg2 scratch — safe, consumed)
    tgemm<0, 0><<<dec_grid, 256, SM_TOT>>>(h, nullptr, whi + OFF_DEC, wlo + OFF_DEC,
                                           nullptr, nullptr, dec_b, nullptr, nullptr, rep, NBP);

    // Householder Q + forward rotate (hv into tmp)
    hh_kernel<<<NN * NB / 256, 256>>>(rep, x, tmp);

    // spectral filter (hv in tmp; output into h)
    spec_fwd<<<dim3(GG, 2), 128>>>(eigvec, tmp, eigval, taus, hs);
    spec_bwd<<<dim3(GG, NPG / 64), 256>>>(eigvec, hs, h);

    // hl = spec_out @ lin_w + lin_b  (into tmp)
    tgemm<0, 0><<<gemm_grid, 256, SM_TOT>>>(h, nullptr, whi + OFF_LIN, wlo + OFF_LIN,
                                            nullptr, nullptr, lin_b, nullptr, nullptr, tmp, CH);

    // out = Q^T @ hl
    final_kernel<<<NN * NB / 256, 256>>>(rep, tmp, out);
}